// round 9
// baseline (speedup 1.0000x reference)
#include <cuda_runtime.h>
#include <cuda_bf16.h>
#include <stdint.h>
#include <stddef.h>

// ============================================================================
// WindowAttention on sm_103 (baseline ISA: mma.sync HMMA, cp.async, ldmatrix)
//   qkv = x @ [Wq|Wk|Wv] + b      (M=100352, K=1024, N=1536, Wv zero-padded)
//   attn = softmax(q k^T * 0.125 + mask[b%256]) ; att = attn @ v
//   out  = att @ Wp + bp          (M=100352, K=512,  N=1024)
// GEMMs: split-bf16 (hi/lo, 3 HMMA passes, lo*lo dropped) fp32 accumulate.
// R9: CTA 128x256, 16 warps (512 thr), warp tile 64x32 -> 4 warps/SMSP to
//     hide LDSM latency under the legacy-HMMA pipe (R8: tensor 60%, 2 w/SMSP).
// ============================================================================

#define M_ROWS   100352
#define N_QKV    1536
#define K_QKV    1024
#define N_PROJ   1024
#define K_PROJ   512

// ---------------- scratch (device globals; no allocation allowed) -----------
__device__ __align__(16) float          g_qkv[(size_t)M_ROWS * N_QKV];
__device__ __align__(16) __nv_bfloat16  g_x_hi[(size_t)M_ROWS * K_QKV];
__device__ __align__(16) __nv_bfloat16  g_x_lo[(size_t)M_ROWS * K_QKV];
__device__ __align__(16) __nv_bfloat16  g_att_hi[(size_t)M_ROWS * K_PROJ];
__device__ __align__(16) __nv_bfloat16  g_att_lo[(size_t)M_ROWS * K_PROJ];
__device__ __align__(16) __nv_bfloat16  g_wqkv_hi[(size_t)N_QKV * K_QKV];
__device__ __align__(16) __nv_bfloat16  g_wqkv_lo[(size_t)N_QKV * K_QKV];
__device__ __align__(16) __nv_bfloat16  g_wp_hi[(size_t)N_PROJ * K_PROJ];
__device__ __align__(16) __nv_bfloat16  g_wp_lo[(size_t)N_PROJ * K_PROJ];
__device__ float g_bqkv[N_QKV];

// ---------------- helpers ----------------------------------------------------
__device__ __forceinline__ uint32_t smem_u32(const void* p) {
    uint32_t a;
    asm("{ .reg .u64 t; cvta.to.shared.u64 t, %1; cvt.u32.u64 %0, t; }"
        : "=r"(a) : "l"(p));
    return a;
}

__device__ __forceinline__ void split_bf16(float x, __nv_bfloat16& h, __nv_bfloat16& l) {
    h = __float2bfloat16_rn(x);
    l = __float2bfloat16_rn(x - __bfloat162float(h));
}

#define CP16(dst, src) \
    asm volatile("cp.async.cg.shared.global [%0], [%1], 16;" \
                 :: "r"(dst), "l"(src))
#define CP_COMMIT() asm volatile("cp.async.commit_group;" ::: "memory")
#define CP_WAIT0()  asm volatile("cp.async.wait_group 0;" ::: "memory")
#define CP_WAIT1()  asm volatile("cp.async.wait_group 1;" ::: "memory")

#define LDMX4(r0, r1, r2, r3, addr) \
    asm volatile("ldmatrix.sync.aligned.m8n8.x4.shared.b16 {%0,%1,%2,%3}, [%4];" \
                 : "=r"(r0), "=r"(r1), "=r"(r2), "=r"(r3) : "r"(addr))

#define MMA16816(d, a, b0, b1) \
    asm volatile("mma.sync.aligned.m16n8k16.row.col.f32.bf16.bf16.f32 " \
                 "{%0,%1,%2,%3}, {%4,%5,%6,%7}, {%8,%9}, {%0,%1,%2,%3};" \
                 : "+f"((d)[0]), "+f"((d)[1]), "+f"((d)[2]), "+f"((d)[3]) \
                 : "r"((a)[0]), "r"((a)[1]), "r"((a)[2]), "r"((a)[3]), \
                   "r"(b0), "r"(b1))

// ============================================================================
// prep: weights (transposed, fused, hi/lo) + bias
// ============================================================================
__global__ void prep_w_kernel(const float* __restrict__ Wq, const float* __restrict__ Wk,
                              const float* __restrict__ Wv, const float* __restrict__ bq,
                              const float* __restrict__ bk, const float* __restrict__ bv,
                              const float* __restrict__ Wp)
{
    const int T1 = N_QKV * K_QKV;
    const int T2 = N_PROJ * K_PROJ;
    const int TOT = T1 + T2 + N_QKV;
    int stride = gridDim.x * blockDim.x;
    for (int idx = blockIdx.x * blockDim.x + threadIdx.x; idx < TOT; idx += stride) {
        if (idx < T1) {
            int n = idx >> 10, k = idx & 1023;
            float w;
            if (n < 512)       w = Wq[k * 512 + n];
            else if (n < 1024) w = Wk[k * 512 + (n - 512)];
            else               w = (k < 512) ? Wv[k * 512 + (n - 1024)] : 0.f;
            __nv_bfloat16 h, l; split_bf16(w, h, l);
            g_wqkv_hi[idx] = h; g_wqkv_lo[idx] = l;
        } else if (idx < T1 + T2) {
            int i = idx - T1;
            int n = i >> 9, k = i & 511;
            float w = Wp[k * 1024 + n];
            __nv_bfloat16 h, l; split_bf16(w, h, l);
            g_wp_hi[i] = h; g_wp_lo[i] = l;
        } else {
            int n = idx - T1 - T2;
            g_bqkv[n] = (n < 512) ? bq[n] : (n < 1024) ? bk[n - 512] : bv[n - 1024];
        }
    }
}

// x[M][1024] f32 -> hi/lo bf16 (8 floats per task)
__global__ void prep_x_kernel(const float* __restrict__ x)
{
    const size_t TOT = (size_t)M_ROWS * K_QKV / 8;
    size_t stride = (size_t)gridDim.x * blockDim.x;
    for (size_t t = blockIdx.x * (size_t)blockDim.x + threadIdx.x; t < TOT; t += stride) {
        const float4* src = (const float4*)(x + t * 8);
        float4 f0 = src[0], f1 = src[1];
        float v[8] = {f0.x, f0.y, f0.z, f0.w, f1.x, f1.y, f1.z, f1.w};
        __nv_bfloat16 h[8], l[8];
        #pragma unroll
        for (int e = 0; e < 8; ++e) split_bf16(v[e], h[e], l[e]);
        *(uint4*)(g_x_hi + t * 8) = *(uint4*)h;
        *(uint4*)(g_x_lo + t * 8) = *(uint4*)l;
    }
}

// ============================================================================
// split-bf16 GEMM: C[M][ldc] = A @ B^T + bias
//   CTA tile 128x256, K-chunk 64, 16 warps (2x8 -> warp tile 64x32)
//   smem/stage: Ahi|Alo (128 rows) + Bhi|Blo (256 rows), 144B padded rows
// ============================================================================
#define ROWB    144                 // padded row bytes (72 bf16)
#define ARRB_A  18432               // 128*144
#define ARRB_B  36864               // 256*144
#define OFF_AL  18432
#define OFF_BH  36864
#define OFF_BL  73728
#define STAGEB  110592              // 2*ARRB_A + 2*ARRB_B
#define GEMM_SMEM (2 * STAGEB)      // 221184

__global__ void __launch_bounds__(512, 1) gemm_kernel(
    const __nv_bfloat16* __restrict__ Ahi, const __nv_bfloat16* __restrict__ Alo, int lda,
    const __nv_bfloat16* __restrict__ Bhi, const __nv_bfloat16* __restrict__ Blo, int ldb,
    const float* __restrict__ bias,
    float* __restrict__ C, int ldc,
    int n_tiles, int k_chunks)
{
    extern __shared__ char smem[];
    uint32_t sbase = smem_u32(smem);
    int tid = threadIdx.x, wid = tid >> 5, lane = tid & 31;
    int nt = blockIdx.x % n_tiles, mt = blockIdx.x / n_tiles;
    int m0 = mt * 128, n0 = nt * 256;

    int warp_m = (wid >> 3) * 64;         // 0 or 64
    int warp_n = (wid & 7) * 32;          // 0,32,...,224

    uint32_t aoff = (uint32_t)((warp_m + (lane & 15)) * ROWB + (lane >> 4) * 16);
    uint32_t boff = (uint32_t)((warp_n + ((lane >> 4) << 3) + (lane & 7)) * ROWB
                               + (((lane >> 3) & 1) << 4));

    float acc[4][4][4];
    #pragma unroll
    for (int i = 0; i < 4; ++i)
        #pragma unroll
        for (int j = 0; j < 4; ++j)
            #pragma unroll
            for (int e = 0; e < 4; ++e) acc[i][j][e] = 0.f;

    auto load_chunk = [&](int c) {
        uint32_t sb = sbase + (uint32_t)(c & 1) * STAGEB;
        const __nv_bfloat16* Ah = Ahi + (size_t)m0 * lda + c * 64;
        const __nv_bfloat16* Al = Alo + (size_t)m0 * lda + c * 64;
        const __nv_bfloat16* Bh = Bhi + (size_t)n0 * ldb + c * 64;
        const __nv_bfloat16* Bl = Blo + (size_t)n0 * ldb + c * 64;
        // A: 2048 16B ops (hi+lo) over 512 threads -> 4 iters
        #pragma unroll
        for (int q = 0; q < 4; ++q) {
            int t = tid + q * 512;
            int sel = t >> 10;
            int r = (t >> 3) & 127, j = t & 7;
            uint32_t dst = sb + (uint32_t)sel * OFF_AL + (uint32_t)(r * ROWB + j * 16);
            const void* src = (sel ? Al : Ah) + (size_t)r * lda + j * 8;
            CP16(dst, src);
        }
        // B: 4096 16B ops (hi+lo) -> 8 iters
        #pragma unroll
        for (int q = 0; q < 8; ++q) {
            int t = tid + q * 512;
            int sel = t >> 11;
            int r = (t >> 3) & 255, j = t & 7;
            uint32_t dst = sb + OFF_BH + (uint32_t)sel * ARRB_B + (uint32_t)(r * ROWB + j * 16);
            const void* src = (sel ? Bl : Bh) + (size_t)r * ldb + j * 8;
            CP16(dst, src);
        }
    };

    load_chunk(0);
    CP_COMMIT();

    for (int c = 0; c < k_chunks; ++c) {
        if (c + 1 < k_chunks) { load_chunk(c + 1); CP_COMMIT(); CP_WAIT1(); }
        else                  { CP_WAIT0(); }
        __syncthreads();

        uint32_t sb = sbase + (uint32_t)(c & 1) * STAGEB;
        uint32_t sAh = sb + aoff;
        uint32_t sAl = sb + OFF_AL + aoff;
        uint32_t sBh = sb + OFF_BH + boff;
        uint32_t sBl = sb + OFF_BL + boff;

        #pragma unroll
        for (int ks = 0; ks < 4; ++ks) {
            uint32_t kb = (uint32_t)(ks * 32);
            uint32_t bh[8], bl[8];
            LDMX4(bh[0], bh[1], bh[2], bh[3], sBh + kb);
            LDMX4(bh[4], bh[5], bh[6], bh[7], sBh + kb + 16 * ROWB);
            LDMX4(bl[0], bl[1], bl[2], bl[3], sBl + kb);
            LDMX4(bl[4], bl[5], bl[6], bl[7], sBl + kb + 16 * ROWB);
            #pragma unroll
            for (int mi = 0; mi < 4; ++mi) {
                uint32_t ah[4], al[4];
                LDMX4(ah[0], ah[1], ah[2], ah[3], sAh + kb + (uint32_t)(mi * 16 * ROWB));
                LDMX4(al[0], al[1], al[2], al[3], sAl + kb + (uint32_t)(mi * 16 * ROWB));
                #pragma unroll
                for (int ni = 0; ni < 4; ++ni) {
                    MMA16816(acc[mi][ni], ah, bh[2 * ni], bh[2 * ni + 1]);
                    MMA16816(acc[mi][ni], ah, bl[2 * ni], bl[2 * ni + 1]);
                    MMA16816(acc[mi][ni], al, bh[2 * ni], bh[2 * ni + 1]);
                }
            }
        }
        __syncthreads();
    }

    // ---- epilogue ----
    #pragma unroll
    for (int mi = 0; mi < 4; ++mi) {
        int m = m0 + warp_m + mi * 16 + (lane >> 2);
        #pragma unroll
        for (int ni = 0; ni < 4; ++ni) {
            int n = n0 + warp_n + ni * 8 + (lane & 3) * 2;
            float b0 = bias[n], b1 = bias[n + 1];
            float2* p0 = (float2*)(C + (size_t)m * ldc + n);
            float2* p1 = (float2*)(C + (size_t)(m + 8) * ldc + n);
            *p0 = make_float2(acc[mi][ni][0] + b0, acc[mi][ni][1] + b1);
            *p1 = make_float2(acc[mi][ni][2] + b0, acc[mi][ni][3] + b1);
        }
    }
}

// ============================================================================
// attention: CTA per (window b, head h); 4-row blocking; smem 43.3KB
// ============================================================================
__global__ void __launch_bounds__(128) attn_kernel(const float* __restrict__ mask)
{
    __shared__ float qs[49 * 68];
    __shared__ float ks[49 * 68];
    __shared__ float vs[49 * 68];
    __shared__ float ps[4][4][52];  // m=49..51 zeroed (ALL 4 warps)

    int b = blockIdx.x, h = blockIdx.y;
    int tid = threadIdx.x, wid = tid >> 5, lane = tid & 31;
    const float* base = g_qkv + (size_t)b * 49 * 1536 + h * 64;

    // zero ps tail for all 4 warps: tid<64 -> w=tid>>4 in 0..3, m in 49..51
    if (tid < 64) {
        int w = tid >> 4, j = (tid >> 2) & 3, m = 49 + (tid & 3);
        if (m < 52) ps[w][j][m] = 0.f;
    }
    // load q/k/v tiles: 3 * 49 * 16 float4
    for (int t = tid; t < 3 * 784; t += 128) {
        int ten = t / 784;
        int rem = t - ten * 784;
        int row = rem >> 4, c4 = rem & 15;
        float4 v4 = *(const float4*)(base + ten * 512 + (size_t)row * 1536 + c4 * 4);
        float* d = (ten == 0 ? qs : ten == 1 ? ks : vs) + row * 68 + c4 * 4;
        *(float4*)d = v4;
    }
    __syncthreads();

    const float* mbase = mask + (size_t)(b & 255) * 2401;
    bool has1 = (lane + 32) < 49;
    int l1row = has1 ? (lane + 32) : 48;       // clamped; result masked via has1
    const float* kr0 = ks + lane * 68;
    const float* kr1 = ks + l1row * 68;

    for (int r0 = wid * 4; r0 < 49; r0 += 16) {
        float a0[4] = {0.f, 0.f, 0.f, 0.f}, a1[4] = {0.f, 0.f, 0.f, 0.f};
        #pragma unroll
        for (int d = 0; d < 64; d += 4) {
            float4 k0 = *(const float4*)(kr0 + d);
            float4 k1 = *(const float4*)(kr1 + d);
            #pragma unroll
            for (int j = 0; j < 4; ++j) {
                int rr = (r0 + j < 49) ? (r0 + j) : 48;
                float4 q4 = *(const float4*)(qs + rr * 68 + d);
                a0[j] += q4.x * k0.x + q4.y * k0.y + q4.z * k0.z + q4.w * k0.w;
                a1[j] += q4.x * k1.x + q4.y * k1.y + q4.z * k1.z + q4.w * k1.w;
            }
        }
        #pragma unroll
        for (int j = 0; j < 4; ++j) {
            int rr = (r0 + j < 49) ? (r0 + j) : 48;
            float m0v = a0[j] * 0.125f + mbase[rr * 49 + lane];
            float m1v = has1 ? (a1[j] * 0.125f + mbase[rr * 49 + lane + 32]) : -1e30f;
            float mx = fmaxf(m0v, m1v);
            #pragma unroll
            for (int o = 16; o; o >>= 1) mx = fmaxf(mx, __shfl_xor_sync(0xFFFFFFFFu, mx, o));
            float e0 = __expf(m0v - mx);
            float e1 = has1 ? __expf(m1v - mx) : 0.f;
            float s = e0 + e1;
            #pragma unroll
            for (int o = 16; o; o >>= 1) s += __shfl_xor_sync(0xFFFFFFFFu, s, o);
            float inv = __fdividef(1.f, s);
            ps[wid][j][lane] = e0 * inv;
            if (has1) ps[wid][j][lane + 32] = e1 * inv;
        }
        __syncwarp();
        float o0[4] = {0.f, 0.f, 0.f, 0.f}, o1[4] = {0.f, 0.f, 0.f, 0.f};
        #pragma unroll
        for (int m4 = 0; m4 < 52; m4 += 4) {
            float4 p[4];
            #pragma unroll
            for (int j = 0; j < 4; ++j) p[j] = *(const float4*)&ps[wid][j][m4];
            #pragma unroll
            for (int mm = 0; mm < 4; ++mm) {
                int mrow = (m4 + mm < 49) ? (m4 + mm) : 48;   // ps zero for m>=49
                float v0 = vs[mrow * 68 + lane];
                float v1 = vs[mrow * 68 + lane + 32];
                #pragma unroll
                for (int j = 0; j < 4; ++j) {
                    float pj = ((const float*)&p[j])[mm];
                    o0[j] += pj * v0;
                    o1[j] += pj * v1;
                }
            }
        }
        #pragma unroll
        for (int j = 0; j < 4; ++j) {
            if (r0 + j < 49) {
                size_t orow = ((size_t)b * 49 + r0 + j) * 512 + h * 64;
                __nv_bfloat16 h0, l0, h1, l1;
                split_bf16(o0[j], h0, l0);
                split_bf16(o1[j], h1, l1);
                g_att_hi[orow + lane]      = h0;
                g_att_lo[orow + lane]      = l0;
                g_att_hi[orow + lane + 32] = h1;
                g_att_lo[orow + lane + 32] = l1;
            }
        }
        __syncwarp();
    }
}

// ============================================================================
// launch
// ============================================================================
extern "C" void kernel_launch(void* const* d_in, const int* in_sizes, int n_in,
                              void* d_out, int out_size)
{
    const float* x    = (const float*)d_in[0];
    const float* mask = (const float*)d_in[1];
    const float* Wq   = (const float*)d_in[2];
    const float* bq   = (const float*)d_in[3];
    const float* Wk   = (const float*)d_in[4];
    const float* bk   = (const float*)d_in[5];
    const float* Wv   = (const float*)d_in[6];
    const float* bv   = (const float*)d_in[7];
    const float* Wp   = (const float*)d_in[8];
    const float* bp   = (const float*)d_in[9];
    float* out = (float*)d_out;

    cudaFuncSetAttribute(gemm_kernel,
                         cudaFuncAttributeMaxDynamicSharedMemorySize, GEMM_SMEM);

    __nv_bfloat16 *xhi, *xlo, *wqh, *wql, *wph, *wpl, *ath, *atl;
    float *qkv, *bqkv;
    cudaGetSymbolAddress((void**)&xhi,  g_x_hi);
    cudaGetSymbolAddress((void**)&xlo,  g_x_lo);
    cudaGetSymbolAddress((void**)&wqh,  g_wqkv_hi);
    cudaGetSymbolAddress((void**)&wql,  g_wqkv_lo);
    cudaGetSymbolAddress((void**)&wph,  g_wp_hi);
    cudaGetSymbolAddress((void**)&wpl,  g_wp_lo);
    cudaGetSymbolAddress((void**)&ath,  g_att_hi);
    cudaGetSymbolAddress((void**)&atl,  g_att_lo);
    cudaGetSymbolAddress((void**)&qkv,  g_qkv);
    cudaGetSymbolAddress((void**)&bqkv, g_bqkv);

    prep_w_kernel<<<1024, 256>>>(Wq, Wk, Wv, bq, bk, bv, Wp);
    prep_x_kernel<<<8192, 256>>>(x);

    // GEMM1a: Q|K columns (n 0..1023), full K=1024 -> 4 n-tiles of 256, kc=16
    gemm_kernel<<<784 * 4, 512, GEMM_SMEM>>>(
        xhi, xlo, K_QKV, wqh, wql, K_QKV, bqkv, qkv, N_QKV, 4, 16);

    // GEMM1b: V columns (n 1024..1535), real K=512 -> 2 n-tiles of 256, kc=8
    gemm_kernel<<<784 * 2, 512, GEMM_SMEM>>>(
        xhi, xlo, K_QKV,
        wqh + (size_t)1024 * K_QKV, wql + (size_t)1024 * K_QKV, K_QKV,
        bqkv + 1024, qkv + 1024, N_QKV, 2, 8);

    // attention (reads g_qkv, writes g_att_hi/lo)
    attn_kernel<<<dim3(2048, 8), 128>>>(mask);

    // GEMM2: out = att @ Wp + bp    (M=100352, K=512, N=1024) -> 4 n-tiles, kc=8
    gemm_kernel<<<784 * 4, 512, GEMM_SMEM>>>(
        ath, atl, K_PROJ, wph, wpl, K_PROJ, bp, out, N_PROJ, 4, 8);
}

// round 10
// speedup vs baseline: 1.5316x; 1.5316x over previous
#include <cuda_runtime.h>
#include <cuda_bf16.h>
#include <stdint.h>
#include <stddef.h>

// ============================================================================
// WindowAttention on sm_103 (baseline ISA: mma.sync HMMA, cp.async, ldmatrix)
//   qkv = x @ [Wq|Wk|Wv] + b      (M=100352, K=1024, N=1536, Wv zero-padded)
//   attn = softmax(q k^T * 0.125 + mask[b%256]) ; att = attn @ v
//   out  = att @ Wp + bp          (M=100352, K=512,  N=1024)
// GEMMs: R8 config (CTA 128x256, 8 warps, warp tile 64x64) — best known.
// R10: attention moved to HMMA (fp32 SIMT attn was at its FFMA roofline).
// ============================================================================

#define M_ROWS   100352
#define N_QKV    1536
#define K_QKV    1024
#define N_PROJ   1024
#define K_PROJ   512

// ---------------- scratch (device globals; no allocation allowed) -----------
__device__ __align__(16) float          g_qkv[(size_t)M_ROWS * N_QKV];
__device__ __align__(16) __nv_bfloat16  g_x_hi[(size_t)M_ROWS * K_QKV];
__device__ __align__(16) __nv_bfloat16  g_x_lo[(size_t)M_ROWS * K_QKV];
__device__ __align__(16) __nv_bfloat16  g_att_hi[(size_t)M_ROWS * K_PROJ];
__device__ __align__(16) __nv_bfloat16  g_att_lo[(size_t)M_ROWS * K_PROJ];
__device__ __align__(16) __nv_bfloat16  g_wqkv_hi[(size_t)N_QKV * K_QKV];
__device__ __align__(16) __nv_bfloat16  g_wqkv_lo[(size_t)N_QKV * K_QKV];
__device__ __align__(16) __nv_bfloat16  g_wp_hi[(size_t)N_PROJ * K_PROJ];
__device__ __align__(16) __nv_bfloat16  g_wp_lo[(size_t)N_PROJ * K_PROJ];
__device__ float g_bqkv[N_QKV];

// ---------------- helpers ----------------------------------------------------
__device__ __forceinline__ uint32_t smem_u32(const void* p) {
    uint32_t a;
    asm("{ .reg .u64 t; cvta.to.shared.u64 t, %1; cvt.u32.u64 %0, t; }"
        : "=r"(a) : "l"(p));
    return a;
}

__device__ __forceinline__ void split_bf16(float x, __nv_bfloat16& h, __nv_bfloat16& l) {
    h = __float2bfloat16_rn(x);
    l = __float2bfloat16_rn(x - __bfloat162float(h));
}

__device__ __forceinline__ uint32_t pack2(__nv_bfloat16 a, __nv_bfloat16 b) {
    return ((uint32_t)__bfloat16_as_ushort(b) << 16) | (uint32_t)__bfloat16_as_ushort(a);
}

#define CP16(dst, src) \
    asm volatile("cp.async.cg.shared.global [%0], [%1], 16;" \
                 :: "r"(dst), "l"(src))
#define CP_COMMIT() asm volatile("cp.async.commit_group;" ::: "memory")
#define CP_WAIT0()  asm volatile("cp.async.wait_group 0;" ::: "memory")
#define CP_WAIT1()  asm volatile("cp.async.wait_group 1;" ::: "memory")

#define LDMX4(r0, r1, r2, r3, addr) \
    asm volatile("ldmatrix.sync.aligned.m8n8.x4.shared.b16 {%0,%1,%2,%3}, [%4];" \
                 : "=r"(r0), "=r"(r1), "=r"(r2), "=r"(r3) : "r"(addr))

#define MMA16816(d, a, b0, b1) \
    asm volatile("mma.sync.aligned.m16n8k16.row.col.f32.bf16.bf16.f32 " \
                 "{%0,%1,%2,%3}, {%4,%5,%6,%7}, {%8,%9}, {%0,%1,%2,%3};" \
                 : "+f"((d)[0]), "+f"((d)[1]), "+f"((d)[2]), "+f"((d)[3]) \
                 : "r"((a)[0]), "r"((a)[1]), "r"((a)[2]), "r"((a)[3]), \
                   "r"(b0), "r"(b1))

// ============================================================================
// prep: weights (transposed, fused, hi/lo) + bias
// ============================================================================
__global__ void prep_w_kernel(const float* __restrict__ Wq, const float* __restrict__ Wk,
                              const float* __restrict__ Wv, const float* __restrict__ bq,
                              const float* __restrict__ bk, const float* __restrict__ bv,
                              const float* __restrict__ Wp)
{
    const int T1 = N_QKV * K_QKV;
    const int T2 = N_PROJ * K_PROJ;
    const int TOT = T1 + T2 + N_QKV;
    int stride = gridDim.x * blockDim.x;
    for (int idx = blockIdx.x * blockDim.x + threadIdx.x; idx < TOT; idx += stride) {
        if (idx < T1) {
            int n = idx >> 10, k = idx & 1023;
            float w;
            if (n < 512)       w = Wq[k * 512 + n];
            else if (n < 1024) w = Wk[k * 512 + (n - 512)];
            else               w = (k < 512) ? Wv[k * 512 + (n - 1024)] : 0.f;
            __nv_bfloat16 h, l; split_bf16(w, h, l);
            g_wqkv_hi[idx] = h; g_wqkv_lo[idx] = l;
        } else if (idx < T1 + T2) {
            int i = idx - T1;
            int n = i >> 9, k = i & 511;
            float w = Wp[k * 1024 + n];
            __nv_bfloat16 h, l; split_bf16(w, h, l);
            g_wp_hi[i] = h; g_wp_lo[i] = l;
        } else {
            int n = idx - T1 - T2;
            g_bqkv[n] = (n < 512) ? bq[n] : (n < 1024) ? bk[n - 512] : bv[n - 1024];
        }
    }
}

// x[M][1024] f32 -> hi/lo bf16 (8 floats per task)
__global__ void prep_x_kernel(const float* __restrict__ x)
{
    const size_t TOT = (size_t)M_ROWS * K_QKV / 8;
    size_t stride = (size_t)gridDim.x * blockDim.x;
    for (size_t t = blockIdx.x * (size_t)blockDim.x + threadIdx.x; t < TOT; t += stride) {
        const float4* src = (const float4*)(x + t * 8);
        float4 f0 = src[0], f1 = src[1];
        float v[8] = {f0.x, f0.y, f0.z, f0.w, f1.x, f1.y, f1.z, f1.w};
        __nv_bfloat16 h[8], l[8];
        #pragma unroll
        for (int e = 0; e < 8; ++e) split_bf16(v[e], h[e], l[e]);
        *(uint4*)(g_x_hi + t * 8) = *(uint4*)h;
        *(uint4*)(g_x_lo + t * 8) = *(uint4*)l;
    }
}

// ============================================================================
// split-bf16 GEMM (R8 verbatim): CTA 128x256, K-chunk 64, 8 warps (64x64)
// ============================================================================
#define ROWB    144                 // padded row bytes (72 bf16)
#define ARRB_A  18432               // 128*144
#define ARRB_B  36864               // 256*144
#define OFF_AL  18432
#define OFF_BH  36864
#define OFF_BL  73728
#define STAGEB  110592              // 2*ARRB_A + 2*ARRB_B
#define GEMM_SMEM (2 * STAGEB)      // 221184

__global__ void __launch_bounds__(256, 1) gemm_kernel(
    const __nv_bfloat16* __restrict__ Ahi, const __nv_bfloat16* __restrict__ Alo, int lda,
    const __nv_bfloat16* __restrict__ Bhi, const __nv_bfloat16* __restrict__ Blo, int ldb,
    const float* __restrict__ bias,
    float* __restrict__ C, int ldc,
    int n_tiles, int k_chunks)
{
    extern __shared__ char smem[];
    uint32_t sbase = smem_u32(smem);
    int tid = threadIdx.x, wid = tid >> 5, lane = tid & 31;
    int nt = blockIdx.x % n_tiles, mt = blockIdx.x / n_tiles;
    int m0 = mt * 128, n0 = nt * 256;

    int warp_m = (wid >> 2) * 64;         // 0 or 64
    int warp_n = (wid & 3) * 64;          // 0,64,128,192

    uint32_t aoff = (uint32_t)((warp_m + (lane & 15)) * ROWB + (lane >> 4) * 16);
    uint32_t boff = (uint32_t)((warp_n + ((lane >> 4) << 3) + (lane & 7)) * ROWB
                               + (((lane >> 3) & 1) << 4));

    float acc[4][8][4];
    #pragma unroll
    for (int i = 0; i < 4; ++i)
        #pragma unroll
        for (int j = 0; j < 8; ++j)
            #pragma unroll
            for (int e = 0; e < 4; ++e) acc[i][j][e] = 0.f;

    auto load_chunk = [&](int c) {
        uint32_t sb = sbase + (uint32_t)(c & 1) * STAGEB;
        const __nv_bfloat16* Ah = Ahi + (size_t)m0 * lda + c * 64;
        const __nv_bfloat16* Al = Alo + (size_t)m0 * lda + c * 64;
        const __nv_bfloat16* Bh = Bhi + (size_t)n0 * ldb + c * 64;
        const __nv_bfloat16* Bl = Blo + (size_t)n0 * ldb + c * 64;
        #pragma unroll
        for (int q = 0; q < 8; ++q) {
            int t = tid + q * 256;
            int sel = t >> 10;
            int r = (t >> 3) & 127, j = t & 7;
            uint32_t dst = sbase + (uint32_t)(c & 1) * STAGEB
                         + (uint32_t)sel * OFF_AL + (uint32_t)(r * ROWB + j * 16);
            const void* src = (sel ? Al : Ah) + (size_t)r * lda + j * 8;
            CP16(dst, src);
        }
        #pragma unroll
        for (int q = 0; q < 16; ++q) {
            int t = tid + q * 256;
            int sel = t >> 11;
            int r = (t >> 3) & 255, j = t & 7;
            uint32_t dst = sb + OFF_BH + (uint32_t)sel * ARRB_B + (uint32_t)(r * ROWB + j * 16);
            const void* src = (sel ? Bl : Bh) + (size_t)r * ldb + j * 8;
            CP16(dst, src);
        }
    };

    load_chunk(0);
    CP_COMMIT();

    for (int c = 0; c < k_chunks; ++c) {
        if (c + 1 < k_chunks) { load_chunk(c + 1); CP_COMMIT(); CP_WAIT1(); }
        else                  { CP_WAIT0(); }
        __syncthreads();

        uint32_t sb = sbase + (uint32_t)(c & 1) * STAGEB;
        uint32_t sAh = sb + aoff;
        uint32_t sAl = sb + OFF_AL + aoff;
        uint32_t sBh = sb + OFF_BH + boff;
        uint32_t sBl = sb + OFF_BL + boff;

        #pragma unroll
        for (int ks = 0; ks < 4; ++ks) {
            uint32_t kb = (uint32_t)(ks * 32);
            uint32_t bh[16], bl[16];
            #pragma unroll
            for (int nb = 0; nb < 4; ++nb) {
                LDMX4(bh[4*nb], bh[4*nb+1], bh[4*nb+2], bh[4*nb+3],
                      sBh + kb + (uint32_t)(nb * 16 * ROWB));
                LDMX4(bl[4*nb], bl[4*nb+1], bl[4*nb+2], bl[4*nb+3],
                      sBl + kb + (uint32_t)(nb * 16 * ROWB));
            }
            #pragma unroll
            for (int mi = 0; mi < 4; ++mi) {
                uint32_t ah[4], al[4];
                LDMX4(ah[0], ah[1], ah[2], ah[3], sAh + kb + (uint32_t)(mi * 16 * ROWB));
                LDMX4(al[0], al[1], al[2], al[3], sAl + kb + (uint32_t)(mi * 16 * ROWB));
                #pragma unroll
                for (int ni = 0; ni < 8; ++ni) {
                    MMA16816(acc[mi][ni], ah, bh[2 * ni], bh[2 * ni + 1]);
                    MMA16816(acc[mi][ni], ah, bl[2 * ni], bl[2 * ni + 1]);
                    MMA16816(acc[mi][ni], al, bh[2 * ni], bh[2 * ni + 1]);
                }
            }
        }
        __syncthreads();
    }

    #pragma unroll
    for (int mi = 0; mi < 4; ++mi) {
        int m = m0 + warp_m + mi * 16 + (lane >> 2);
        #pragma unroll
        for (int ni = 0; ni < 8; ++ni) {
            int n = n0 + warp_n + ni * 8 + (lane & 3) * 2;
            float b0 = bias[n], b1 = bias[n + 1];
            float2* p0 = (float2*)(C + (size_t)m * ldc + n);
            float2* p1 = (float2*)(C + (size_t)(m + 8) * ldc + n);
            *p0 = make_float2(acc[mi][ni][0] + b0, acc[mi][ni][1] + b1);
            *p1 = make_float2(acc[mi][ni][2] + b0, acc[mi][ni][3] + b1);
        }
    }
}

// ============================================================================
// HMMA attention: CTA per (window b, head h), 4 warps.
// Tiles padded to 64. Split-bf16 Q,K (3-pass QK^T), fp32 softmax in C-frags,
// P fed to PV via C-frag->A-frag packing (hi/lo, drop Plo*Vlo), V^T in smem.
// ============================================================================
#define AT_QH 0
#define AT_QL 9216
#define AT_KH 18432
#define AT_KL 27648
#define AT_VH 36864
#define AT_VL 46080
#define ATTN_SMEM 55296

__global__ void __launch_bounds__(128) attn_kernel(const float* __restrict__ mask)
{
    extern __shared__ char sm[];
    uint32_t sb = smem_u32(sm);
    int b = blockIdx.x, h = blockIdx.y;
    int tid = threadIdx.x, wid = tid >> 5, lane = tid & 31;

    // zero smem (padded rows/cols must be 0 for MMA)
    #pragma unroll 4
    for (int i = tid; i < ATTN_SMEM / 16; i += 128)
        ((uint4*)sm)[i] = make_uint4(0u, 0u, 0u, 0u);
    __syncthreads();

    const float* base = g_qkv + (size_t)b * 49 * 1536 + h * 64;

    // Q,K: 49x64 f32 -> hi/lo bf16, 144B rows
    for (int t = tid; t < 1568; t += 128) {
        int ten = (t >= 784) ? 1 : 0;
        int rem = t - ten * 784;
        int row = rem >> 4, c4 = rem & 15;
        float4 v = *(const float4*)(base + ten * 512 + (size_t)row * 1536 + c4 * 4);
        __nv_bfloat16 hx, lx, hy, ly, hz, lz, hw, lw;
        split_bf16(v.x, hx, lx); split_bf16(v.y, hy, ly);
        split_bf16(v.z, hz, lz); split_bf16(v.w, hw, lw);
        char* dh = sm + (ten ? AT_KH : AT_QH) + row * 144 + c4 * 8;
        char* dl = sm + (ten ? AT_KL : AT_QL) + row * 144 + c4 * 8;
        ((uint32_t*)dh)[0] = pack2(hx, hy); ((uint32_t*)dh)[1] = pack2(hz, hw);
        ((uint32_t*)dl)[0] = pack2(lx, ly); ((uint32_t*)dl)[1] = pack2(lz, lw);
    }
    // V transposed: VT[d][token], hi/lo
    for (int t = tid; t < 784; t += 128) {
        int row = t >> 4, c4 = t & 15;
        float4 v = *(const float4*)(base + 1024 + (size_t)row * 1536 + c4 * 4);
        float vv[4] = {v.x, v.y, v.z, v.w};
        #pragma unroll
        for (int i = 0; i < 4; ++i) {
            int d = c4 * 4 + i;
            __nv_bfloat16 hh, ll; split_bf16(vv[i], hh, ll);
            *(__nv_bfloat16*)(sm + AT_VH + d * 144 + row * 2) = hh;
            *(__nv_bfloat16*)(sm + AT_VL + d * 144 + row * 2) = ll;
        }
    }
    __syncthreads();

    uint32_t aoff = (uint32_t)((wid * 16 + (lane & 15)) * 144 + (lane >> 4) * 16);
    uint32_t boff = (uint32_t)(((((lane >> 4) << 3)) + (lane & 7)) * 144
                               + (((lane >> 3) & 1) << 4));

    // ---- QK^T (3 passes) ----
    float qa[8][4];
    #pragma unroll
    for (int ni = 0; ni < 8; ++ni)
        #pragma unroll
        for (int e = 0; e < 4; ++e) qa[ni][e] = 0.f;

    #pragma unroll
    for (int ks = 0; ks < 4; ++ks) {
        uint32_t kb = (uint32_t)(ks * 32);
        uint32_t bh[16], bl[16], ah[4], al[4];
        #pragma unroll
        for (int nb = 0; nb < 4; ++nb) {
            LDMX4(bh[4*nb], bh[4*nb+1], bh[4*nb+2], bh[4*nb+3],
                  sb + AT_KH + boff + kb + (uint32_t)(nb * 16 * 144));
            LDMX4(bl[4*nb], bl[4*nb+1], bl[4*nb+2], bl[4*nb+3],
                  sb + AT_KL + boff + kb + (uint32_t)(nb * 16 * 144));
        }
        LDMX4(ah[0], ah[1], ah[2], ah[3], sb + AT_QH + aoff + kb);
        LDMX4(al[0], al[1], al[2], al[3], sb + AT_QL + aoff + kb);
        #pragma unroll
        for (int ni = 0; ni < 8; ++ni) {
            MMA16816(qa[ni], ah, bh[2 * ni], bh[2 * ni + 1]);
            MMA16816(qa[ni], ah, bl[2 * ni], bl[2 * ni + 1]);
            MMA16816(qa[ni], al, bh[2 * ni], bh[2 * ni + 1]);
        }
    }

    // ---- mask + softmax in registers ----
    int r0 = wid * 16 + (lane >> 2), r1 = r0 + 8;
    const float* mb = mask + (size_t)(b & 255) * 2401;
    #pragma unroll
    for (int ni = 0; ni < 8; ++ni) {
        int c = ni * 8 + (lane & 3) * 2;
        if (r0 < 49) {
            if (c < 49)     qa[ni][0] = qa[ni][0] * 0.125f + mb[r0 * 49 + c];
            else            qa[ni][0] = -1e30f;
            if (c + 1 < 49) qa[ni][1] = qa[ni][1] * 0.125f + mb[r0 * 49 + c + 1];
            else            qa[ni][1] = -1e30f;
        } else {
            qa[ni][0] = (c < 49) ? 0.f : -1e30f;
            qa[ni][1] = (c + 1 < 49) ? 0.f : -1e30f;
        }
        if (r1 < 49) {
            if (c < 49)     qa[ni][2] = qa[ni][2] * 0.125f + mb[r1 * 49 + c];
            else            qa[ni][2] = -1e30f;
            if (c + 1 < 49) qa[ni][3] = qa[ni][3] * 0.125f + mb[r1 * 49 + c + 1];
            else            qa[ni][3] = -1e30f;
        } else {
            qa[ni][2] = (c < 49) ? 0.f : -1e30f;
            qa[ni][3] = (c + 1 < 49) ? 0.f : -1e30f;
        }
    }
    float mx0 = -1e30f, mx1 = -1e30f;
    #pragma unroll
    for (int ni = 0; ni < 8; ++ni) {
        mx0 = fmaxf(mx0, fmaxf(qa[ni][0], qa[ni][1]));
        mx1 = fmaxf(mx1, fmaxf(qa[ni][2], qa[ni][3]));
    }
    mx0 = fmaxf(mx0, __shfl_xor_sync(0xFFFFFFFFu, mx0, 1));
    mx0 = fmaxf(mx0, __shfl_xor_sync(0xFFFFFFFFu, mx0, 2));
    mx1 = fmaxf(mx1, __shfl_xor_sync(0xFFFFFFFFu, mx1, 1));
    mx1 = fmaxf(mx1, __shfl_xor_sync(0xFFFFFFFFu, mx1, 2));
    float s0 = 0.f, s1 = 0.f;
    #pragma unroll
    for (int ni = 0; ni < 8; ++ni) {
        qa[ni][0] = __expf(qa[ni][0] - mx0); s0 += qa[ni][0];
        qa[ni][1] = __expf(qa[ni][1] - mx0); s0 += qa[ni][1];
        qa[ni][2] = __expf(qa[ni][2] - mx1); s1 += qa[ni][2];
        qa[ni][3] = __expf(qa[ni][3] - mx1); s1 += qa[ni][3];
    }
    s0 += __shfl_xor_sync(0xFFFFFFFFu, s0, 1);
    s0 += __shfl_xor_sync(0xFFFFFFFFu, s0, 2);
    s1 += __shfl_xor_sync(0xFFFFFFFFu, s1, 1);
    s1 += __shfl_xor_sync(0xFFFFFFFFu, s1, 2);
    float i0 = __fdividef(1.f, s0), i1 = __fdividef(1.f, s1);
    #pragma unroll
    for (int ni = 0; ni < 8; ++ni) {
        qa[ni][0] *= i0; qa[ni][1] *= i0;
        qa[ni][2] *= i1; qa[ni][3] *= i1;
    }

    // ---- P @ V (3 passes; P A-frags packed from C-frags) ----
    float oa[8][4];
    #pragma unroll
    for (int ni = 0; ni < 8; ++ni)
        #pragma unroll
        for (int e = 0; e < 4; ++e) oa[ni][e] = 0.f;

    #pragma unroll
    for (int kk = 0; kk < 4; ++kk) {
        int n0i = 2 * kk, n1i = 2 * kk + 1;
        uint32_t ah[4], al[4];
        {
            __nv_bfloat16 ha, la, hb, lb;
            split_bf16(qa[n0i][0], ha, la); split_bf16(qa[n0i][1], hb, lb);
            ah[0] = pack2(ha, hb); al[0] = pack2(la, lb);
            split_bf16(qa[n0i][2], ha, la); split_bf16(qa[n0i][3], hb, lb);
            ah[1] = pack2(ha, hb); al[1] = pack2(la, lb);
            split_bf16(qa[n1i][0], ha, la); split_bf16(qa[n1i][1], hb, lb);
            ah[2] = pack2(ha, hb); al[2] = pack2(la, lb);
            split_bf16(qa[n1i][2], ha, la); split_bf16(qa[n1i][3], hb, lb);
            ah[3] = pack2(ha, hb); al[3] = pack2(la, lb);
        }
        uint32_t kb = (uint32_t)(kk * 32);
        uint32_t bvh[16], bvl[16];
        #pragma unroll
        for (int nb = 0; nb < 4; ++nb) {
            LDMX4(bvh[4*nb], bvh[4*nb+1], bvh[4*nb+2], bvh[4*nb+3],
                  sb + AT_VH + boff + kb + (uint32_t)(nb * 16 * 144));
            LDMX4(bvl[4*nb], bvl[4*nb+1], bvl[4*nb+2], bvl[4*nb+3],
                  sb + AT_VL + boff + kb + (uint32_t)(nb * 16 * 144));
        }
        #pragma unroll
        for (int ni = 0; ni < 8; ++ni) {
            MMA16816(oa[ni], ah, bvh[2 * ni], bvh[2 * ni + 1]);
            MMA16816(oa[ni], ah, bvl[2 * ni], bvl[2 * ni + 1]);
            MMA16816(oa[ni], al, bvh[2 * ni], bvh[2 * ni + 1]);
        }
    }

    // ---- store (hi/lo bf16) ----
    #pragma unroll
    for (int ni = 0; ni < 8; ++ni) {
        int c = ni * 8 + (lane & 3) * 2;
        if (r0 < 49) {
            size_t o = ((size_t)b * 49 + r0) * 512 + h * 64 + c;
            __nv_bfloat16 h0, l0, h1, l1;
            split_bf16(oa[ni][0], h0, l0); split_bf16(oa[ni][1], h1, l1);
            *(uint32_t*)&g_att_hi[o] = pack2(h0, h1);
            *(uint32_t*)&g_att_lo[o] = pack2(l0, l1);
        }
        if (r1 < 49) {
            size_t o = ((size_t)b * 49 + r1) * 512 + h * 64 + c;
            __nv_bfloat16 h0, l0, h1, l1;
            split_bf16(oa[ni][2], h0, l0); split_bf16(oa[ni][3], h1, l1);
            *(uint32_t*)&g_att_hi[o] = pack2(h0, h1);
            *(uint32_t*)&g_att_lo[o] = pack2(l0, l1);
        }
    }
}

// ============================================================================
// launch
// ============================================================================
extern "C" void kernel_launch(void* const* d_in, const int* in_sizes, int n_in,
                              void* d_out, int out_size)
{
    const float* x    = (const float*)d_in[0];
    const float* mask = (const float*)d_in[1];
    const float* Wq   = (const float*)d_in[2];
    const float* bq   = (const float*)d_in[3];
    const float* Wk   = (const float*)d_in[4];
    const float* bk   = (const float*)d_in[5];
    const float* Wv   = (const float*)d_in[6];
    const float* bv   = (const float*)d_in[7];
    const float* Wp   = (const float*)d_in[8];
    const float* bp   = (const float*)d_in[9];
    float* out = (float*)d_out;

    cudaFuncSetAttribute(gemm_kernel,
                         cudaFuncAttributeMaxDynamicSharedMemorySize, GEMM_SMEM);
    cudaFuncSetAttribute(attn_kernel,
                         cudaFuncAttributeMaxDynamicSharedMemorySize, ATTN_SMEM);

    __nv_bfloat16 *xhi, *xlo, *wqh, *wql, *wph, *wpl, *ath, *atl;
    float *qkv, *bqkv;
    cudaGetSymbolAddress((void**)&xhi,  g_x_hi);
    cudaGetSymbolAddress((void**)&xlo,  g_x_lo);
    cudaGetSymbolAddress((void**)&wqh,  g_wqkv_hi);
    cudaGetSymbolAddress((void**)&wql,  g_wqkv_lo);
    cudaGetSymbolAddress((void**)&wph,  g_wp_hi);
    cudaGetSymbolAddress((void**)&wpl,  g_wp_lo);
    cudaGetSymbolAddress((void**)&ath,  g_att_hi);
    cudaGetSymbolAddress((void**)&atl,  g_att_lo);
    cudaGetSymbolAddress((void**)&qkv,  g_qkv);
    cudaGetSymbolAddress((void**)&bqkv, g_bqkv);

    prep_w_kernel<<<1024, 256>>>(Wq, Wk, Wv, bq, bk, bv, Wp);
    prep_x_kernel<<<8192, 256>>>(x);

    // GEMM1a: Q|K columns (n 0..1023), full K=1024 -> 4 n-tiles of 256, kc=16
    gemm_kernel<<<784 * 4, 256, GEMM_SMEM>>>(
        xhi, xlo, K_QKV, wqh, wql, K_QKV, bqkv, qkv, N_QKV, 4, 16);

    // GEMM1b: V columns (n 1024..1535), real K=512 -> 2 n-tiles of 256, kc=8
    gemm_kernel<<<784 * 2, 256, GEMM_SMEM>>>(
        xhi, xlo, K_QKV,
        wqh + (size_t)1024 * K_QKV, wql + (size_t)1024 * K_QKV, K_QKV,
        bqkv + 1024, qkv + 1024, N_QKV, 2, 8);

    // attention (reads g_qkv, writes g_att_hi/lo) — HMMA path
    attn_kernel<<<dim3(2048, 8), 128, ATTN_SMEM>>>(mask);

    // GEMM2: out = att @ Wp + bp    (M=100352, K=512, N=1024) -> 4 n-tiles, kc=8
    gemm_kernel<<<784 * 4, 256, GEMM_SMEM>>>(
        ath, atl, K_PROJ, wph, wpl, K_PROJ, bp, out, N_PROJ, 4, 8);
}